// round 10
// baseline (speedup 1.0000x reference)
#include <cuda_runtime.h>
#include <cuda_fp16.h>
#include <stdint.h>

#define NB   4
#define CIN  256
#define COUT 256
#define HH   96
#define WW   96
#define HWSZ (HH*WW)          // 9216
#define KK2  9
#define CK   (CIN*KK2)        // 2304
#define NOFF 18
#define NCHUNK 36             // CK / 64
#define KC   64
#define ZSPLIT 8
#define PX   64               // pixels per CTA
#define NT   512              // threads per CTA
#define WP   97               // padded pair-row width
#define CSTR (HH*WP)          // channel stride in pairs (9312)

// ---- dynamic smem layout for dcn_hmma (bytes) ----
#define BSTRIDE   72
#define BBUF_U32  (32*BSTRIDE)          // 2304 u32 = 9216 B
#define BBUF_BYTES (BBUF_U32*4)         // 9216 B
#define OFF_IDX    (2*BBUF_BYTES)       // 18432 (int2[9][64] = 4608 B)
#define OFF_SWT    (OFF_IDX + KK2*PX*8) // 23040 (float4[9][64] = 9216 B)
#define SMEM_BYTES (OFF_SWT + KK2*PX*16)// 32256

// ---- device scratch (allocation-free rule) ----
__device__ float    g_off_part[ZSPLIT*NB*NOFF*HWSZ];   // 21 MB
__device__ float    g_offset[NB*NOFF*HWSZ];            // 2.65 MB
__device__ uint32_t g_wfrag[NCHUNK*16*32*16];          // 1.18 MB: fp16 A fragments
__device__ uint32_t g_xpair[NB*CIN*CSTR];              // 38.1 MB: fp16x2 (x[i-1],x[i]) pairs

// ---------------------------------------------------------------------------
// Kernel A1: partial offset conv (32 Cin channels per block.z chunk)
// ---------------------------------------------------------------------------
__global__ __launch_bounds__(128) void offset_part(
    const float* __restrict__ x, const float* __restrict__ w_off)
{
    __shared__ float ws[8*NOFF*KK2];
    int b   = blockIdx.y, z = blockIdx.z;
    int tid = threadIdx.x;
    int p0  = blockIdx.x * 256 + tid;
    int p1  = p0 + 128;
    int yy0 = p0 / WW, xx0 = p0 % WW;
    int yy1 = p1 / WW, xx1 = p1 % WW;

    float acc[2][NOFF];
    #pragma unroll
    for (int j = 0; j < NOFF; j++) { acc[0][j] = 0.f; acc[1][j] = 0.f; }

    const float* xb = x + (size_t)b * CIN * HWSZ;
    const int CPZ = CIN / ZSPLIT;   // 32

    for (int c0 = z*CPZ; c0 < z*CPZ + CPZ; c0 += 8) {
        __syncthreads();
        for (int l = tid; l < 8*NOFF*KK2; l += 128) {
            int ci = l / (NOFF*KK2);
            int r  = l % (NOFF*KK2);
            int j  = r / KK2, k = r % KK2;
            ws[l] = w_off[((size_t)(j*CIN + c0 + ci))*KK2 + k];
        }
        __syncthreads();
        #pragma unroll 2
        for (int ci = 0; ci < 8; ci++) {
            const float* xp = xb + (size_t)(c0 + ci) * HWSZ;
            float xv0[9], xv1[9];
            #pragma unroll
            for (int ky = 0; ky < 3; ky++) {
                #pragma unroll
                for (int kx = 0; kx < 3; kx++) {
                    int iy = yy0 - 1 + ky, ix = xx0 - 1 + kx;
                    xv0[ky*3+kx] = (iy >= 0 && iy < HH && ix >= 0 && ix < WW) ? xp[iy*WW + ix] : 0.f;
                    iy = yy1 - 1 + ky; ix = xx1 - 1 + kx;
                    xv1[ky*3+kx] = (iy >= 0 && iy < HH && ix >= 0 && ix < WW) ? xp[iy*WW + ix] : 0.f;
                }
            }
            const float* wsc = ws + ci * NOFF * KK2;
            #pragma unroll
            for (int j = 0; j < NOFF; j++) {
                #pragma unroll
                for (int k = 0; k < KK2; k++) {
                    float wv = wsc[j*KK2 + k];
                    acc[0][j] += xv0[k] * wv;
                    acc[1][j] += xv1[k] * wv;
                }
            }
        }
    }
    size_t zb = (size_t)z * NB * NOFF * HWSZ;
    #pragma unroll
    for (int j = 0; j < NOFF; j++) {
        g_off_part[zb + ((size_t)b*NOFF + j)*HWSZ + p0] = acc[0][j];
        g_off_part[zb + ((size_t)b*NOFF + j)*HWSZ + p1] = acc[1][j];
    }
}

// Kernel A2: sum partials + bias
__global__ void offset_reduce(const float* __restrict__ b_off)
{
    int i = blockIdx.x * 256 + threadIdx.x;
    if (i < NB*NOFF*HWSZ) {
        int j = (i / HWSZ) % NOFF;
        float s = b_off[j];
        #pragma unroll
        for (int z = 0; z < ZSPLIT; z++) s += g_off_part[(size_t)z*NB*NOFF*HWSZ + i];
        g_offset[i] = s;
    }
}

// ---------------------------------------------------------------------------
// Kernel B1: pack w_def into fp16 A-fragments (m16n8k16 layout).
// ---------------------------------------------------------------------------
__global__ void wprep(const float* __restrict__ w_def)
{
    int idx = blockIdx.x * 256 + threadIdx.x;
    if (idx >= NCHUNK*16*32*16) return;
    int i     =  idx        & 3;
    int lane  = (idx >> 2)  & 31;
    int ks    = (idx >> 7)  & 3;
    int mb    = (idx >> 9)  & 15;
    int chunk =  idx >> 13;

    int o = mb*16 + (lane >> 2) + (i & 1)*8;
    int k = chunk*64 + ks*16 + (lane & 3)*2 + (i >> 1)*8;
    float w0 = w_def[(size_t)o*CK + k];
    float w1 = w_def[(size_t)o*CK + k + 1];

    __half2 v = __floats2half2_rn(w0, w1);
    g_wfrag[idx] = *(uint32_t*)&v;
}

// ---------------------------------------------------------------------------
// Kernel B2: build zero-padded fp16 pair table.
// g_xpair[row][pi] = (x[row][pi-1] or 0, x[row][pi] or 0),  pi in [0,96]
// ---------------------------------------------------------------------------
__global__ void xprep(const float* __restrict__ x)
{
    int i = blockIdx.x * 256 + threadIdx.x;
    if (i >= NB*CIN*CSTR) return;
    int pi   = i % WP;
    int row  = i / WP;                 // b*CIN*HH + c*HH + y
    const float* rp = x + (size_t)row * WW;
    float lo = (pi >= 1)      ? rp[pi-1] : 0.f;
    float hi = (pi <= WW - 1) ? rp[pi]   : 0.f;
    __half2 h = __floats2half2_rn(lo, hi);
    g_xpair[i] = *(uint32_t*)&h;
}

// ---------------------------------------------------------------------------
__device__ __forceinline__ void mma16816(float* c, uint4 a, uint32_t b0, uint32_t b1)
{
    asm volatile(
        "mma.sync.aligned.m16n8k16.row.col.f32.f16.f16.f32 "
        "{%0,%1,%2,%3}, {%4,%5,%6,%7}, {%8,%9}, {%0,%1,%2,%3};"
        : "+f"(c[0]), "+f"(c[1]), "+f"(c[2]), "+f"(c[3])
        : "r"(a.x), "r"(a.y), "r"(a.z), "r"(a.w), "r"(b0), "r"(b1));
}

// ---------------------------------------------------------------------------
// Kernel C: fused bilinear-gather (fp16 pair loads) + fp16 HMMA GEMM.
// CTA: 64 px x 256 Cout; 512 threads = 16 warps (4 m-rows x 4 n-cols),
// warp tile 64 x 16. grid 576, 2 CTAs/SM.
// ---------------------------------------------------------------------------
__global__ void __launch_bounds__(NT, 2) dcn_hmma(
    const float* __restrict__ x,
    float* __restrict__ out,
    const float* __restrict__ b_def)
{
    extern __shared__ __align__(16) unsigned char smem_raw[];
    int2*   s_idx = (int2*)  (smem_raw + OFF_IDX);
    float4* s_wt  = (float4*)(smem_raw + OFF_SWT);

    int tid = threadIdx.x, wid = tid >> 5, lane = tid & 31;
    int mrow = wid >> 2, ncol = wid & 3;

    int gp    = blockIdx.x * PX;
    int b     = gp / HWSZ;
    int pbase = gp % HWSZ;

    // Phase 1: pair indices & weights. wx validity folded by zero-padding;
    // out-of-range pair index zeroes wx; y validity folded into wy.
    for (int l = tid; l < KK2*PX; l += NT) {
        int k2 = l >> 6, pl = l & 63;
        int p  = pbase + pl;
        int oy = p / WW, ox = p % WW;
        float offy = g_offset[((size_t)b*NOFF + k2*2    )*HWSZ + p];
        float offx = g_offset[((size_t)b*NOFF + k2*2 + 1)*HWSZ + p];
        int ky = k2 / 3, kx = k2 % 3;
        float py = (float)(oy - 1 + ky) + offy;
        float px = (float)(ox - 1 + kx) + offx;
        float y0f = floorf(py), x0f = floorf(px);
        float wy1 = py - y0f, wy0 = 1.f - wy1;
        float wx1 = px - x0f, wx0 = 1.f - wx1;
        int iy0 = (int)y0f, ix0 = (int)x0f;
        int iy1 = iy0 + 1;
        int pir = ix0 + 1;                       // pair index
        bool inx = (pir >= 0) && (pir <= WP - 1);
        int pi  = min(max(pir, 0), WP - 1);
        bool vy0 = (iy0 >= 0) && (iy0 < HH), vy1 = (iy1 >= 0) && (iy1 < HH);
        int cy0 = min(max(iy0, 0), HH-1), cy1 = min(max(iy1, 0), HH-1);
        s_idx[l] = make_int2(cy0*WP + pi, cy1*WP + pi);
        s_wt[l]  = make_float4(inx ? wx0 : 0.f, inx ? wx1 : 0.f,
                               vy0 ? wy0 : 0.f, vy1 ? wy1 : 0.f);
    }
    __syncthreads();

    const uint32_t* xb_pair = g_xpair + (size_t)b * CIN * CSTR;
    const uint4* wfrag4 = (const uint4*)g_wfrag;

    float acc[4][2][4];
    #pragma unroll
    for (int i = 0; i < 4; i++)
        #pragma unroll
        for (int j = 0; j < 2; j++)
            #pragma unroll
            for (int e = 0; e < 4; e++) acc[i][j][e] = 0.f;

    // ---- gather (2 pair-loads per k-value) + fp16 pack into buffer bb ----
    auto gather_store = [&](int chunk, int bb) {
        uint32_t* sB = (uint32_t*)(smem_raw + bb * BBUF_BYTES);
        int ck0 = chunk * KC;
        #pragma unroll
        for (int it = 0; it < 4; it++) {
            int l  = it*NT + tid;
            int kp = l >> 6, pl = l & 63;
            int ck = ck0 + kp*2;
            int c  = ck / 9, k2 = ck - c*9;
            int2   id = s_idx[k2*PX + pl];
            float4 w  = s_wt [k2*PX + pl];
            const uint32_t* xp = xb_pair + (size_t)c * CSTR;
            uint32_t u0 = __ldg(xp + id.x), u1 = __ldg(xp + id.y);
            float2 a0 = __half22float2(*(__half2*)&u0);
            float2 a1 = __half22float2(*(__half2*)&u1);
            float v0 = w.z*(w.x*a0.x + w.y*a0.y) + w.w*(w.x*a1.x + w.y*a1.y);

            int ck1 = ck + 1;
            int c1  = ck1 / 9, k21 = ck1 - c1*9;
            id = s_idx[k21*PX + pl];
            w  = s_wt [k21*PX + pl];
            xp = xb_pair + (size_t)c1 * CSTR;
            u0 = __ldg(xp + id.x); u1 = __ldg(xp + id.y);
            a0 = __half22float2(*(__half2*)&u0);
            a1 = __half22float2(*(__half2*)&u1);
            float v1 = w.z*(w.x*a0.x + w.y*a0.y) + w.w*(w.x*a1.x + w.y*a1.y);

            __half2 hv = __floats2half2_rn(v0, v1);
            sB[kp*BSTRIDE + pl] = *(uint32_t*)&hv;
        }
    };

    // prologue: fill buffer 0 with chunk 0
    gather_store(0, 0);
    __syncthreads();

    #pragma unroll 1
    for (int chunk = 0; chunk < NCHUNK; ++chunk) {
        if (chunk + 1 < NCHUNK) gather_store(chunk + 1, (chunk + 1) & 1);

        uint32_t* sB = (uint32_t*)(smem_raw + (chunk & 1) * BBUF_BYTES);

        #pragma unroll
        for (int ks = 0; ks < 4; ks++) {
            uint32_t bh0[2], bh1[2];
            #pragma unroll
            for (int nb = 0; nb < 2; nb++) {
                int col = ncol*16 + nb*8 + (lane >> 2);
                int kpb = ks*8 + (lane & 3);
                bh0[nb] = sB[ kpb     *BSTRIDE + col];
                bh1[nb] = sB[(kpb + 4)*BSTRIDE + col];
            }
            #pragma unroll
            for (int mb = 0; mb < 4; mb++) {
                int mbg = mrow*4 + mb;
                uint4 a = __ldg(wfrag4 + ((size_t)(chunk*16 + mbg)*4 + ks)*32 + lane);
                #pragma unroll
                for (int nb = 0; nb < 2; nb++)
                    mma16816(acc[mb][nb], a, bh0[nb], bh1[nb]);
            }
        }
        __syncthreads();
    }

    // ---- epilogue: bias + store ----
    #pragma unroll
    for (int mb = 0; mb < 4; mb++) {
        int o0 = mrow*64 + mb*16 + (lane >> 2);
        float bd0 = b_def[o0], bd8 = b_def[o0 + 8];
        float* r0 = out + ((size_t)b*COUT + o0)*HWSZ + pbase + ncol*16 + (lane & 3)*2;
        float* r8 = r0 + (size_t)8*HWSZ;
        #pragma unroll
        for (int nb = 0; nb < 2; nb++) {
            float2 v0 = make_float2(acc[mb][nb][0] + bd0, acc[mb][nb][1] + bd0);
            float2 v8 = make_float2(acc[mb][nb][2] + bd8, acc[mb][nb][3] + bd8);
            *(float2*)(r0 + nb*8) = v0;
            *(float2*)(r8 + nb*8) = v8;
        }
    }
}

// ---------------------------------------------------------------------------
extern "C" void kernel_launch(void* const* d_in, const int* in_sizes, int n_in,
                              void* d_out, int out_size)
{
    const float* x     = (const float*)d_in[0];
    const float* w_off = (const float*)d_in[1];
    const float* b_off = (const float*)d_in[2];
    const float* w_def = (const float*)d_in[3];
    const float* b_def = (const float*)d_in[4];
    float* out = (float*)d_out;

    cudaFuncSetAttribute(dcn_hmma, cudaFuncAttributeMaxDynamicSharedMemorySize, SMEM_BYTES);

    offset_part<<<dim3(HWSZ/256, NB, ZSPLIT), 128>>>(x, w_off);
    xprep<<<(NB*CIN*CSTR + 255)/256, 256>>>(x);
    wprep<<<(NCHUNK*16*32*16 + 255)/256, 256>>>(w_def);
    offset_reduce<<<(NB*NOFF*HWSZ + 255)/256, 256>>>(b_off);
    dcn_hmma<<<NB*HWSZ/PX, NT, SMEM_BYTES>>>(x, out, b_def);
}

// round 11
// speedup vs baseline: 1.1333x; 1.1333x over previous
#include <cuda_runtime.h>
#include <cuda_fp16.h>
#include <stdint.h>

#define NB   4
#define CIN  256
#define COUT 256
#define HH   96
#define WW   96
#define HWSZ (HH*WW)          // 9216
#define KK2  9
#define CK   (CIN*KK2)        // 2304
#define NOFF 18
#define NCHUNK 36             // CK / 64
#define KC   64
#define ZSPLIT 8
#define PX   64               // pixels per CTA
#define NT   256              // threads per CTA
#define WP   97               // padded pair-row width
#define CSTR (HH*WP)          // channel stride in pairs (9312)

// ---- dynamic smem layout for dcn_hmma (bytes) ----
#define BSTRIDE   72
#define BBUF_U32  (32*BSTRIDE)          // 2304 u32 = 9216 B
#define BBUF_BYTES (BBUF_U32*4)         // 9216 B
#define OFF_IDX    (2*BBUF_BYTES)       // 18432 (int2[9][64] = 4608 B)
#define OFF_SWT    (OFF_IDX + KK2*PX*8) // 23040 (float4[9][64] = 9216 B)
#define SMEM_BYTES (OFF_SWT + KK2*PX*16)// 32256

// ---- device scratch (allocation-free rule) ----
__device__ float    g_off_part[ZSPLIT*NB*NOFF*HWSZ];   // 21 MB
__device__ float    g_offset[NB*NOFF*HWSZ];            // 2.65 MB
__device__ uint32_t g_wfrag[NCHUNK*16*32*16];          // 1.18 MB: fp16 A fragments
__device__ uint32_t g_xpair[NB*CIN*CSTR];              // 38.1 MB: fp16x2 (x[i-1],x[i]) pairs

// ---------------------------------------------------------------------------
// Kernel A1: partial offset conv (32 Cin channels per block.z chunk)
// ---------------------------------------------------------------------------
__global__ __launch_bounds__(128) void offset_part(
    const float* __restrict__ x, const float* __restrict__ w_off)
{
    __shared__ float ws[8*NOFF*KK2];
    int b   = blockIdx.y, z = blockIdx.z;
    int tid = threadIdx.x;
    int p0  = blockIdx.x * 256 + tid;
    int p1  = p0 + 128;
    int yy0 = p0 / WW, xx0 = p0 % WW;
    int yy1 = p1 / WW, xx1 = p1 % WW;

    float acc[2][NOFF];
    #pragma unroll
    for (int j = 0; j < NOFF; j++) { acc[0][j] = 0.f; acc[1][j] = 0.f; }

    const float* xb = x + (size_t)b * CIN * HWSZ;
    const int CPZ = CIN / ZSPLIT;   // 32

    for (int c0 = z*CPZ; c0 < z*CPZ + CPZ; c0 += 8) {
        __syncthreads();
        for (int l = tid; l < 8*NOFF*KK2; l += 128) {
            int ci = l / (NOFF*KK2);
            int r  = l % (NOFF*KK2);
            int j  = r / KK2, k = r % KK2;
            ws[l] = w_off[((size_t)(j*CIN + c0 + ci))*KK2 + k];
        }
        __syncthreads();
        #pragma unroll 2
        for (int ci = 0; ci < 8; ci++) {
            const float* xp = xb + (size_t)(c0 + ci) * HWSZ;
            float xv0[9], xv1[9];
            #pragma unroll
            for (int ky = 0; ky < 3; ky++) {
                #pragma unroll
                for (int kx = 0; kx < 3; kx++) {
                    int iy = yy0 - 1 + ky, ix = xx0 - 1 + kx;
                    xv0[ky*3+kx] = (iy >= 0 && iy < HH && ix >= 0 && ix < WW) ? xp[iy*WW + ix] : 0.f;
                    iy = yy1 - 1 + ky; ix = xx1 - 1 + kx;
                    xv1[ky*3+kx] = (iy >= 0 && iy < HH && ix >= 0 && ix < WW) ? xp[iy*WW + ix] : 0.f;
                }
            }
            const float* wsc = ws + ci * NOFF * KK2;
            #pragma unroll
            for (int j = 0; j < NOFF; j++) {
                #pragma unroll
                for (int k = 0; k < KK2; k++) {
                    float wv = wsc[j*KK2 + k];
                    acc[0][j] += xv0[k] * wv;
                    acc[1][j] += xv1[k] * wv;
                }
            }
        }
    }
    size_t zb = (size_t)z * NB * NOFF * HWSZ;
    #pragma unroll
    for (int j = 0; j < NOFF; j++) {
        g_off_part[zb + ((size_t)b*NOFF + j)*HWSZ + p0] = acc[0][j];
        g_off_part[zb + ((size_t)b*NOFF + j)*HWSZ + p1] = acc[1][j];
    }
}

// Kernel A2: sum partials + bias
__global__ void offset_reduce(const float* __restrict__ b_off)
{
    int i = blockIdx.x * 256 + threadIdx.x;
    if (i < NB*NOFF*HWSZ) {
        int j = (i / HWSZ) % NOFF;
        float s = b_off[j];
        #pragma unroll
        for (int z = 0; z < ZSPLIT; z++) s += g_off_part[(size_t)z*NB*NOFF*HWSZ + i];
        g_offset[i] = s;
    }
}

// ---------------------------------------------------------------------------
// Kernel B1: pack w_def into fp16 A-fragments (m16n8k16 layout).
// ---------------------------------------------------------------------------
__global__ void wprep(const float* __restrict__ w_def)
{
    int idx = blockIdx.x * 256 + threadIdx.x;
    if (idx >= NCHUNK*16*32*16) return;
    int i     =  idx        & 3;
    int lane  = (idx >> 2)  & 31;
    int ks    = (idx >> 7)  & 3;
    int mb    = (idx >> 9)  & 15;
    int chunk =  idx >> 13;

    int o = mb*16 + (lane >> 2) + (i & 1)*8;
    int k = chunk*64 + ks*16 + (lane & 3)*2 + (i >> 1)*8;
    float w0 = w_def[(size_t)o*CK + k];
    float w1 = w_def[(size_t)o*CK + k + 1];

    __half2 v = __floats2half2_rn(w0, w1);
    g_wfrag[idx] = *(uint32_t*)&v;
}

// ---------------------------------------------------------------------------
// Kernel B2: build zero-padded fp16 pair table.
// g_xpair[row][pi] = (x[row][pi-1] or 0, x[row][pi] or 0),  pi in [0,96]
// ---------------------------------------------------------------------------
__global__ void xprep(const float* __restrict__ x)
{
    int i = blockIdx.x * 256 + threadIdx.x;
    if (i >= NB*CIN*CSTR) return;
    int pi   = i % WP;
    int row  = i / WP;                 // b*CIN*HH + c*HH + y
    const float* rp = x + (size_t)row * WW;
    float lo = (pi >= 1)      ? rp[pi-1] : 0.f;
    float hi = (pi <= WW - 1) ? rp[pi]   : 0.f;
    __half2 h = __floats2half2_rn(lo, hi);
    g_xpair[i] = *(uint32_t*)&h;
}

// ---------------------------------------------------------------------------
__device__ __forceinline__ void mma16816(float* c, uint4 a, uint32_t b0, uint32_t b1)
{
    asm volatile(
        "mma.sync.aligned.m16n8k16.row.col.f32.f16.f16.f32 "
        "{%0,%1,%2,%3}, {%4,%5,%6,%7}, {%8,%9}, {%0,%1,%2,%3};"
        : "+f"(c[0]), "+f"(c[1]), "+f"(c[2]), "+f"(c[3])
        : "r"(a.x), "r"(a.y), "r"(a.z), "r"(a.w), "r"(b0), "r"(b1));
}

// ---------------------------------------------------------------------------
// Kernel C: fused bilinear-gather (fp16 pair loads, MLP-batched) + fp16 HMMA.
// CTA: 64 px x 256 Cout; 256 threads = 8 warps (4 m-rows x 2 n-cols),
// warp tile 64 x 32. grid 576, 2 CTAs/SM.
// ---------------------------------------------------------------------------
__global__ void __launch_bounds__(NT, 2) dcn_hmma(
    const float* __restrict__ x,
    float* __restrict__ out,
    const float* __restrict__ b_def)
{
    extern __shared__ __align__(16) unsigned char smem_raw[];
    int2*   s_idx = (int2*)  (smem_raw + OFF_IDX);
    float4* s_wt  = (float4*)(smem_raw + OFF_SWT);

    int tid = threadIdx.x, wid = tid >> 5, lane = tid & 31;
    int mrow = wid >> 1, ncol = wid & 1;

    int gp    = blockIdx.x * PX;
    int b     = gp / HWSZ;
    int pbase = gp % HWSZ;

    // Phase 1: pair indices & weights (x validity via zero-padding; y via wy)
    for (int l = tid; l < KK2*PX; l += NT) {
        int k2 = l >> 6, pl = l & 63;
        int p  = pbase + pl;
        int oy = p / WW, ox = p % WW;
        float offy = g_offset[((size_t)b*NOFF + k2*2    )*HWSZ + p];
        float offx = g_offset[((size_t)b*NOFF + k2*2 + 1)*HWSZ + p];
        int ky = k2 / 3, kx = k2 % 3;
        float py = (float)(oy - 1 + ky) + offy;
        float px = (float)(ox - 1 + kx) + offx;
        float y0f = floorf(py), x0f = floorf(px);
        float wy1 = py - y0f, wy0 = 1.f - wy1;
        float wx1 = px - x0f, wx0 = 1.f - wx1;
        int iy0 = (int)y0f, ix0 = (int)x0f;
        int iy1 = iy0 + 1;
        int pir = ix0 + 1;                       // pair index
        bool inx = (pir >= 0) && (pir <= WP - 1);
        int pi  = min(max(pir, 0), WP - 1);
        bool vy0 = (iy0 >= 0) && (iy0 < HH), vy1 = (iy1 >= 0) && (iy1 < HH);
        int cy0 = min(max(iy0, 0), HH-1), cy1 = min(max(iy1, 0), HH-1);
        s_idx[l] = make_int2(cy0*WP + pi, cy1*WP + pi);
        s_wt[l]  = make_float4(inx ? wx0 : 0.f, inx ? wx1 : 0.f,
                               vy0 ? wy0 : 0.f, vy1 ? wy1 : 0.f);
    }
    __syncthreads();

    const uint32_t* xb_pair = g_xpair + (size_t)b * CIN * CSTR;
    const uint4* wfrag4 = (const uint4*)g_wfrag;

    float acc[4][4][4];
    #pragma unroll
    for (int i = 0; i < 4; i++)
        #pragma unroll
        for (int j = 0; j < 4; j++)
            #pragma unroll
            for (int e = 0; e < 4; e++) acc[i][j][e] = 0.f;

    // ---- gather: 2 halves x (load 16 LDGs batched, then compute+STS) ----
    auto gather_store = [&](int chunk, int bb) {
        uint32_t* sB = (uint32_t*)(smem_raw + bb * BBUF_BYTES);
        int ck0 = chunk * KC;
        #pragma unroll
        for (int half = 0; half < 2; half++) {
            uint32_t u[16];
            // --- load phase: 16 independent LDGs in flight ---
            #pragma unroll
            for (int e = 0; e < 4; e++) {
                int l  = (half*4 + e)*NT + tid;
                int kp = l >> 6, pl = l & 63;
                int ck = ck0 + kp*2;
                int c  = ck / 9, k2 = ck - c*9;
                int2 id0 = s_idx[k2*PX + pl];
                const uint32_t* xp = xb_pair + (size_t)c * CSTR;
                u[e*4+0] = __ldg(xp + id0.x);
                u[e*4+1] = __ldg(xp + id0.y);
                int ck1 = ck + 1;
                int c1  = ck1 / 9, k21 = ck1 - c1*9;
                int2 id1 = s_idx[k21*PX + pl];
                const uint32_t* xq = xb_pair + (size_t)c1 * CSTR;
                u[e*4+2] = __ldg(xq + id1.x);
                u[e*4+3] = __ldg(xq + id1.y);
            }
            // --- compute phase ---
            #pragma unroll
            for (int e = 0; e < 4; e++) {
                int l  = (half*4 + e)*NT + tid;
                int kp = l >> 6, pl = l & 63;
                int ck = ck0 + kp*2;
                int c  = ck / 9, k2 = ck - c*9;
                float4 w = s_wt[k2*PX + pl];
                float2 a0 = __half22float2(*(__half2*)&u[e*4+0]);
                float2 a1 = __half22float2(*(__half2*)&u[e*4+1]);
                float v0 = w.z*(w.x*a0.x + w.y*a0.y) + w.w*(w.x*a1.x + w.y*a1.y);
                int ck1 = ck + 1;
                int c1  = ck1 / 9, k21 = ck1 - c1*9;
                w = s_wt[k21*PX + pl];
                a0 = __half22float2(*(__half2*)&u[e*4+2]);
                a1 = __half22float2(*(__half2*)&u[e*4+3]);
                float v1 = w.z*(w.x*a0.x + w.y*a0.y) + w.w*(w.x*a1.x + w.y*a1.y);
                __half2 hv = __floats2half2_rn(v0, v1);
                sB[kp*BSTRIDE + pl] = *(uint32_t*)&hv;
            }
        }
    };

    // prologue: fill buffer 0 with chunk 0
    gather_store(0, 0);
    __syncthreads();

    #pragma unroll 1
    for (int chunk = 0; chunk < NCHUNK; ++chunk) {
        if (chunk + 1 < NCHUNK) gather_store(chunk + 1, (chunk + 1) & 1);

        uint32_t* sB = (uint32_t*)(smem_raw + (chunk & 1) * BBUF_BYTES);

        // ---- HMMA: single fp16 pass, warp tile 64x32 ----
        #pragma unroll
        for (int ks = 0; ks < 4; ks++) {
            uint32_t bh0[4], bh1[4];
            #pragma unroll
            for (int nb = 0; nb < 4; nb++) {
                int col = ncol*32 + nb*8 + (lane >> 2);
                int kpb = ks*8 + (lane & 3);
                bh0[nb] = sB[ kpb     *BSTRIDE + col];
                bh1[nb] = sB[(kpb + 4)*BSTRIDE + col];
            }
            #pragma unroll
            for (int mb = 0; mb < 4; mb++) {
                int mbg = mrow*4 + mb;
                uint4 a = __ldg(wfrag4 + ((size_t)(chunk*16 + mbg)*4 + ks)*32 + lane);
                #pragma unroll
                for (int nb = 0; nb < 4; nb++)
                    mma16816(acc[mb][nb], a, bh0[nb], bh1[nb]);
            }
        }
        __syncthreads();
    }

    // ---- epilogue: bias + store ----
    #pragma unroll
    for (int mb = 0; mb < 4; mb++) {
        int o0 = mrow*64 + mb*16 + (lane >> 2);
        float bd0 = b_def[o0], bd8 = b_def[o0 + 8];
        float* r0 = out + ((size_t)b*COUT + o0)*HWSZ + pbase + ncol*32 + (lane & 3)*2;
        float* r8 = r0 + (size_t)8*HWSZ;
        #pragma unroll
        for (int nb = 0; nb < 4; nb++) {
            float2 v0 = make_float2(acc[mb][nb][0] + bd0, acc[mb][nb][1] + bd0);
            float2 v8 = make_float2(acc[mb][nb][2] + bd8, acc[mb][nb][3] + bd8);
            *(float2*)(r0 + nb*8) = v0;
            *(float2*)(r8 + nb*8) = v8;
        }
    }
}

// ---------------------------------------------------------------------------
extern "C" void kernel_launch(void* const* d_in, const int* in_sizes, int n_in,
                              void* d_out, int out_size)
{
    const float* x     = (const float*)d_in[0];
    const float* w_off = (const float*)d_in[1];
    const float* b_off = (const float*)d_in[2];
    const float* w_def = (const float*)d_in[3];
    const float* b_def = (const float*)d_in[4];
    float* out = (float*)d_out;

    cudaFuncSetAttribute(dcn_hmma, cudaFuncAttributeMaxDynamicSharedMemorySize, SMEM_BYTES);

    offset_part<<<dim3(HWSZ/256, NB, ZSPLIT), 128>>>(x, w_off);
    xprep<<<(NB*CIN*CSTR + 255)/256, 256>>>(x);
    wprep<<<(NCHUNK*16*32*16 + 255)/256, 256>>>(w_def);
    offset_reduce<<<(NB*NOFF*HWSZ + 255)/256, 256>>>(b_off);
    dcn_hmma<<<NB*HWSZ/PX, NT, SMEM_BYTES>>>(x, out, b_def);
}

// round 12
// speedup vs baseline: 1.1529x; 1.0173x over previous
#include <cuda_runtime.h>
#include <cuda_fp16.h>
#include <stdint.h>

#define NB   4
#define CIN  256
#define COUT 256
#define HH   96
#define WW   96
#define HWSZ (HH*WW)          // 9216
#define KK2  9
#define CK   (CIN*KK2)        // 2304
#define NOFF 18
#define NCHUNK 36             // CK / 64
#define KC   64
#define ZSPLIT 8
#define PX   64               // pixels per CTA
#define NT   256              // threads per CTA
#define WP   97               // padded pair-row width
#define CSTR (HH*WP)          // channel stride in pairs (9312)

#define NWF  (NCHUNK*16*32*16)   // wfrag elements
#define NXP  (NB*CIN*CSTR)       // xpair elements

// ---- dynamic smem layout for dcn_hmma (bytes) ----
#define BSTRIDE   72
#define BBUF_U32  (32*BSTRIDE)          // 2304 u32 = 9216 B
#define BBUF_BYTES (BBUF_U32*4)         // 9216 B
#define OFF_IDX    (2*BBUF_BYTES)       // 18432 (int2[9][64] = 4608 B)
#define OFF_SWT    (OFF_IDX + KK2*PX*8) // 23040 (float4[9][64] = 9216 B)
#define SMEM_BYTES (OFF_SWT + KK2*PX*16)// 32256

// ---- device scratch (allocation-free rule) ----
__device__ float    g_off_part[ZSPLIT*NB*NOFF*HWSZ];   // 21 MB
__device__ float    g_offset[NB*NOFF*HWSZ];            // 2.65 MB
__device__ uint32_t g_wfrag[NWF];                      // 1.18 MB: fp16 A fragments
__device__ uint32_t g_xpair[NXP];                      // 38.1 MB: fp16x2 pairs

// ---- packed f32x2 helpers ----
typedef unsigned long long u64t;
__device__ __forceinline__ u64t pack2(float lo, float hi) {
    u64t r; asm("mov.b64 %0, {%1, %2};" : "=l"(r) : "f"(lo), "f"(hi)); return r;
}
__device__ __forceinline__ void fma2(u64t& acc, u64t a, u64t b) {
    asm("fma.rn.f32x2 %0, %1, %2, %0;" : "+l"(acc) : "l"(a), "l"(b));
}
__device__ __forceinline__ float2 unpack2(u64t v) {
    float2 f; asm("mov.b64 {%0, %1}, %2;" : "=f"(f.x), "=f"(f.y) : "l"(v)); return f;
}

// ---------------------------------------------------------------------------
// Kernel A1: partial offset conv, packed f32x2 FMA, 4 px/thread.
// grid (HWSZ/512 = 18, NB, ZSPLIT), 128 threads.
// ---------------------------------------------------------------------------
__global__ __launch_bounds__(128) void offset_part(
    const float* __restrict__ x, const float* __restrict__ w_off)
{
    __shared__ float ws[8*NOFF*KK2];
    int b   = blockIdx.y, z = blockIdx.z;
    int tid = threadIdx.x;
    int p0  = blockIdx.x * 512 + tid;

    int yy[4], xx[4];
    #pragma unroll
    for (int i = 0; i < 4; i++) { int p = p0 + i*128; yy[i] = p / WW; xx[i] = p % WW; }

    u64t acc2[2][NOFF];
    #pragma unroll
    for (int j = 0; j < NOFF; j++) { acc2[0][j] = 0ULL; acc2[1][j] = 0ULL; }

    const float* xb = x + (size_t)b * CIN * HWSZ;
    const int CPZ = CIN / ZSPLIT;   // 32

    for (int c0 = z*CPZ; c0 < z*CPZ + CPZ; c0 += 8) {
        __syncthreads();
        for (int l = tid; l < 8*NOFF*KK2; l += 128) {
            int ci = l / (NOFF*KK2);
            int r  = l % (NOFF*KK2);
            int j  = r / KK2, k = r % KK2;
            ws[l] = w_off[((size_t)(j*CIN + c0 + ci))*KK2 + k];
        }
        __syncthreads();
        #pragma unroll 2
        for (int ci = 0; ci < 8; ci++) {
            const float* xp = xb + (size_t)(c0 + ci) * HWSZ;
            u64t xv2a[9], xv2b[9];
            #pragma unroll
            for (int ky = 0; ky < 3; ky++) {
                #pragma unroll
                for (int kx = 0; kx < 3; kx++) {
                    float v[4];
                    #pragma unroll
                    for (int i = 0; i < 4; i++) {
                        int iy = yy[i] - 1 + ky, ix = xx[i] - 1 + kx;
                        v[i] = (iy >= 0 && iy < HH && ix >= 0 && ix < WW) ? xp[iy*WW + ix] : 0.f;
                    }
                    xv2a[ky*3+kx] = pack2(v[0], v[1]);
                    xv2b[ky*3+kx] = pack2(v[2], v[3]);
                }
            }
            const float* wsc = ws + ci * NOFF * KK2;
            #pragma unroll
            for (int j = 0; j < NOFF; j++) {
                #pragma unroll
                for (int k = 0; k < KK2; k++) {
                    float w = wsc[j*KK2 + k];
                    u64t w2 = pack2(w, w);
                    fma2(acc2[0][j], xv2a[k], w2);
                    fma2(acc2[1][j], xv2b[k], w2);
                }
            }
        }
    }
    size_t zb = (size_t)z * NB * NOFF * HWSZ;
    #pragma unroll
    for (int j = 0; j < NOFF; j++) {
        float2 a = unpack2(acc2[0][j]);
        float2 c = unpack2(acc2[1][j]);
        size_t base = zb + ((size_t)b*NOFF + j)*HWSZ + p0;
        g_off_part[base        ] = a.x;
        g_off_part[base + 128  ] = a.y;
        g_off_part[base + 256  ] = c.x;
        g_off_part[base + 384  ] = c.y;
    }
}

// Kernel A2: sum partials + bias
__global__ void offset_reduce(const float* __restrict__ b_off)
{
    int i = blockIdx.x * 256 + threadIdx.x;
    if (i < NB*NOFF*HWSZ) {
        int j = (i / HWSZ) % NOFF;
        float s = b_off[j];
        #pragma unroll
        for (int z = 0; z < ZSPLIT; z++) s += g_off_part[(size_t)z*NB*NOFF*HWSZ + i];
        g_offset[i] = s;
    }
}

// ---------------------------------------------------------------------------
// Kernel B (fused): wfrag pack + xpair table.
// ---------------------------------------------------------------------------
__global__ void prep(const float* __restrict__ w_def, const float* __restrict__ x)
{
    int i = blockIdx.x * 256 + threadIdx.x;
    if (i < NWF) {
        int idx = i;
        int ii    =  idx        & 3;
        int lane  = (idx >> 2)  & 31;
        int ks    = (idx >> 7)  & 3;
        int mb    = (idx >> 9)  & 15;
        int chunk =  idx >> 13;
        int o = mb*16 + (lane >> 2) + (ii & 1)*8;
        int k = chunk*64 + ks*16 + (lane & 3)*2 + (ii >> 1)*8;
        float w0 = w_def[(size_t)o*CK + k];
        float w1 = w_def[(size_t)o*CK + k + 1];
        __half2 v = __floats2half2_rn(w0, w1);
        g_wfrag[idx] = *(uint32_t*)&v;
    } else {
        int j = i - NWF;
        if (j < NXP) {
            int pi  = j % WP;
            int row = j / WP;              // b*CIN*HH + c*HH + y
            const float* rp = x + (size_t)row * WW;
            float lo = (pi >= 1)      ? rp[pi-1] : 0.f;
            float hi = (pi <= WW - 1) ? rp[pi]   : 0.f;
            __half2 h = __floats2half2_rn(lo, hi);
            g_xpair[j] = *(uint32_t*)&h;
        }
    }
}

// ---------------------------------------------------------------------------
__device__ __forceinline__ void mma16816(float* c, uint4 a, uint32_t b0, uint32_t b1)
{
    asm volatile(
        "mma.sync.aligned.m16n8k16.row.col.f32.f16.f16.f32 "
        "{%0,%1,%2,%3}, {%4,%5,%6,%7}, {%8,%9}, {%0,%1,%2,%3};"
        : "+f"(c[0]), "+f"(c[1]), "+f"(c[2]), "+f"(c[3])
        : "r"(a.x), "r"(a.y), "r"(a.z), "r"(a.w), "r"(b0), "r"(b1));
}

// ---------------------------------------------------------------------------
// Kernel C: fused bilinear-gather (fp16 pair loads, MLP-batched) + fp16 HMMA.
// CTA: 64 px x 256 Cout; 256 threads = 8 warps (4 m-rows x 2 n-cols),
// warp tile 64 x 32. grid 576, 2 CTAs/SM.   (unchanged from round 11)
// ---------------------------------------------------------------------------
__global__ void __launch_bounds__(NT, 2) dcn_hmma(
    const float* __restrict__ x,
    float* __restrict__ out,
    const float* __restrict__ b_def)
{
    extern __shared__ __align__(16) unsigned char smem_raw[];
    int2*   s_idx = (int2*)  (smem_raw + OFF_IDX);
    float4* s_wt  = (float4*)(smem_raw + OFF_SWT);

    int tid = threadIdx.x, wid = tid >> 5, lane = tid & 31;
    int mrow = wid >> 1, ncol = wid & 1;

    int gp    = blockIdx.x * PX;
    int b     = gp / HWSZ;
    int pbase = gp % HWSZ;

    // Phase 1: pair indices & weights (x validity via zero-padding; y via wy)
    for (int l = tid; l < KK2*PX; l += NT) {
        int k2 = l >> 6, pl = l & 63;
        int p  = pbase + pl;
        int oy = p / WW, ox = p % WW;
        float offy = g_offset[((size_t)b*NOFF + k2*2    )*HWSZ + p];
        float offx = g_offset[((size_t)b*NOFF + k2*2 + 1)*HWSZ + p];
        int ky = k2 / 3, kx = k2 % 3;
        float py = (float)(oy - 1 + ky) + offy;
        float px = (float)(ox - 1 + kx) + offx;
        float y0f = floorf(py), x0f = floorf(px);
        float wy1 = py - y0f, wy0 = 1.f - wy1;
        float wx1 = px - x0f, wx0 = 1.f - wx1;
        int iy0 = (int)y0f, ix0 = (int)x0f;
        int iy1 = iy0 + 1;
        int pir = ix0 + 1;                       // pair index
        bool inx = (pir >= 0) && (pir <= WP - 1);
        int pi  = min(max(pir, 0), WP - 1);
        bool vy0 = (iy0 >= 0) && (iy0 < HH), vy1 = (iy1 >= 0) && (iy1 < HH);
        int cy0 = min(max(iy0, 0), HH-1), cy1 = min(max(iy1, 0), HH-1);
        s_idx[l] = make_int2(cy0*WP + pi, cy1*WP + pi);
        s_wt[l]  = make_float4(inx ? wx0 : 0.f, inx ? wx1 : 0.f,
                               vy0 ? wy0 : 0.f, vy1 ? wy1 : 0.f);
    }
    __syncthreads();

    const uint32_t* xb_pair = g_xpair + (size_t)b * CIN * CSTR;
    const uint4* wfrag4 = (const uint4*)g_wfrag;

    float acc[4][4][4];
    #pragma unroll
    for (int i = 0; i < 4; i++)
        #pragma unroll
        for (int j = 0; j < 4; j++)
            #pragma unroll
            for (int e = 0; e < 4; e++) acc[i][j][e] = 0.f;

    // ---- gather: 2 halves x (load 16 LDGs batched, then compute+STS) ----
    auto gather_store = [&](int chunk, int bb) {
        uint32_t* sB = (uint32_t*)(smem_raw + bb * BBUF_BYTES);
        int ck0 = chunk * KC;
        #pragma unroll
        for (int half = 0; half < 2; half++) {
            uint32_t u[16];
            #pragma unroll
            for (int e = 0; e < 4; e++) {
                int l  = (half*4 + e)*NT + tid;
                int kp = l >> 6, pl = l & 63;
                int ck = ck0 + kp*2;
                int c  = ck / 9, k2 = ck - c*9;
                int2 id0 = s_idx[k2*PX + pl];
                const uint32_t* xp = xb_pair + (size_t)c * CSTR;
                u[e*4+0] = __ldg(xp + id0.x);
                u[e*4+1] = __ldg(xp + id0.y);
                int ck1 = ck + 1;
                int c1  = ck1 / 9, k21 = ck1 - c1*9;
                int2 id1 = s_idx[k21*PX + pl];
                const uint32_t* xq = xb_pair + (size_t)c1 * CSTR;
                u[e*4+2] = __ldg(xq + id1.x);
                u[e*4+3] = __ldg(xq + id1.y);
            }
            #pragma unroll
            for (int e = 0; e < 4; e++) {
                int l  = (half*4 + e)*NT + tid;
                int kp = l >> 6, pl = l & 63;
                int ck = ck0 + kp*2;
                int c  = ck / 9, k2 = ck - c*9;
                float4 w = s_wt[k2*PX + pl];
                float2 a0 = __half22float2(*(__half2*)&u[e*4+0]);
                float2 a1 = __half22float2(*(__half2*)&u[e*4+1]);
                float v0 = w.z*(w.x*a0.x + w.y*a0.y) + w.w*(w.x*a1.x + w.y*a1.y);
                int ck1 = ck + 1;
                int c1  = ck1 / 9, k21 = ck1 - c1*9;
                w = s_wt[k21*PX + pl];
                a0 = __half22float2(*(__half2*)&u[e*4+2]);
                a1 = __half22float2(*(__half2*)&u[e*4+3]);
                float v1 = w.z*(w.x*a0.x + w.y*a0.y) + w.w*(w.x*a1.x + w.y*a1.y);
                __half2 hv = __floats2half2_rn(v0, v1);
                sB[kp*BSTRIDE + pl] = *(uint32_t*)&hv;
            }
        }
    };

    gather_store(0, 0);
    __syncthreads();

    #pragma unroll 1
    for (int chunk = 0; chunk < NCHUNK; ++chunk) {
        if (chunk + 1 < NCHUNK) gather_store(chunk + 1, (chunk + 1) & 1);

        uint32_t* sB = (uint32_t*)(smem_raw + (chunk & 1) * BBUF_BYTES);

        #pragma unroll
        for (int ks = 0; ks < 4; ks++) {
            uint32_t bh0[4], bh1[4];
            #pragma unroll
            for (int nb = 0; nb < 4; nb++) {
                int col = ncol*32 + nb*8 + (lane >> 2);
                int kpb = ks*8 + (lane & 3);
                bh0[nb] = sB[ kpb     *BSTRIDE + col];
                bh1[nb] = sB[(kpb + 4)*BSTRIDE + col];
            }
            #pragma unroll
            for (int mb = 0; mb < 4; mb++) {
                int mbg = mrow*4 + mb;
                uint4 a = __ldg(wfrag4 + ((size_t)(chunk*16 + mbg)*4 + ks)*32 + lane);
                #pragma unroll
                for (int nb = 0; nb < 4; nb++)
                    mma16816(acc[mb][nb], a, bh0[nb], bh1[nb]);
            }
        }
        __syncthreads();
    }

    // ---- epilogue: bias + store ----
    #pragma unroll
    for (int mb = 0; mb < 4; mb++) {
        int o0 = mrow*64 + mb*16 + (lane >> 2);
        float bd0 = b_def[o0], bd8 = b_def[o0 + 8];
        float* r0 = out + ((size_t)b*COUT + o0)*HWSZ + pbase + ncol*32 + (lane & 3)*2;
        float* r8 = r0 + (size_t)8*HWSZ;
        #pragma unroll
        for (int nb = 0; nb < 4; nb++) {
            float2 v0 = make_float2(acc[mb][nb][0] + bd0, acc[mb][nb][1] + bd0);
            float2 v8 = make_float2(acc[mb][nb][2] + bd8, acc[mb][nb][3] + bd8);
            *(float2*)(r0 + nb*8) = v0;
            *(float2*)(r8 + nb*8) = v8;
        }
    }
}

// ---------------------------------------------------------------------------
extern "C" void kernel_launch(void* const* d_in, const int* in_sizes, int n_in,
                              void* d_out, int out_size)
{
    const float* x     = (const float*)d_in[0];
    const float* w_off = (const float*)d_in[1];
    const float* b_off = (const float*)d_in[2];
    const float* w_def = (const float*)d_in[3];
    const float* b_def = (const float*)d_in[4];
    float* out = (float*)d_out;

    cudaFuncSetAttribute(dcn_hmma, cudaFuncAttributeMaxDynamicSharedMemorySize, SMEM_BYTES);

    offset_part<<<dim3(HWSZ/512, NB, ZSPLIT), 128>>>(x, w_off);
    prep<<<(NWF + NXP + 255)/256, 256>>>(w_def, x);
    offset_reduce<<<(NB*NOFF*HWSZ + 255)/256, 256>>>(b_off);
    dcn_hmma<<<NB*HWSZ/PX, NT, SMEM_BYTES>>>(x, out, b_def);
}

// round 13
// speedup vs baseline: 1.1851x; 1.0279x over previous
#include <cuda_runtime.h>
#include <cuda_fp16.h>
#include <stdint.h>

#define NB   4
#define CIN  256
#define COUT 256
#define HH   96
#define WW   96
#define HWSZ (HH*WW)          // 9216
#define KK2  9
#define CK   (CIN*KK2)        // 2304
#define NOFF 18
#define NCHUNK 36             // CK / 64
#define KC   64
#define ZSPLIT 8
#define PX   64               // pixels per CTA
#define NT   256              // threads per CTA
#define WP   97               // padded pair-row width
#define CSTR (HH*WP)          // channel stride in pairs (9312)

#define NWF  (NCHUNK*16*32*16)   // wfrag elements
#define NXP  (NB*CIN*CSTR)       // xpair elements

// ---- dynamic smem layout for dcn_hmma (bytes) ----
#define BSTRIDE   72
#define BBUF_U32  (32*BSTRIDE)          // 2304 u32 = 9216 B
#define BBUF_BYTES (BBUF_U32*4)         // 9216 B
#define OFF_IDX    (2*BBUF_BYTES)       // 18432: int4[64][9]  = 9216 B
#define OFF_WQ     (OFF_IDX + PX*9*16)  // 27648: uint4[64][9] = 9216 B
#define SMEM_BYTES (OFF_WQ + PX*9*16)   // 36864

// ---- device scratch (allocation-free rule) ----
__device__ float    g_off_part[ZSPLIT*NB*NOFF*HWSZ];   // 21 MB
__device__ float    g_offset[NB*NOFF*HWSZ];            // 2.65 MB
__device__ uint32_t g_wfrag[NWF];                      // 1.18 MB: fp16 A fragments
__device__ uint32_t g_xpair[NXP];                      // 38.1 MB: fp16x2 pairs

// ---- packed f32x2 helpers ----
typedef unsigned long long u64t;
__device__ __forceinline__ u64t pack2(float lo, float hi) {
    u64t r; asm("mov.b64 %0, {%1, %2};" : "=l"(r) : "f"(lo), "f"(hi)); return r;
}
__device__ __forceinline__ void fma2(u64t& acc, u64t a, u64t b) {
    asm("fma.rn.f32x2 %0, %1, %2, %0;" : "+l"(acc) : "l"(a), "l"(b));
}
__device__ __forceinline__ float2 unpack2(u64t v) {
    float2 f; asm("mov.b64 {%0, %1}, %2;" : "=f"(f.x), "=f"(f.y) : "l"(v)); return f;
}

// ---------------------------------------------------------------------------
// Kernel A1: partial offset conv, packed f32x2 FMA, 4 px/thread.
// grid (HWSZ/512 = 18, NB, ZSPLIT), 128 threads.
// ---------------------------------------------------------------------------
__global__ __launch_bounds__(128) void offset_part(
    const float* __restrict__ x, const float* __restrict__ w_off)
{
    __shared__ float ws[8*NOFF*KK2];
    int b   = blockIdx.y, z = blockIdx.z;
    int tid = threadIdx.x;
    int p0  = blockIdx.x * 512 + tid;

    int yy[4], xx[4];
    #pragma unroll
    for (int i = 0; i < 4; i++) { int p = p0 + i*128; yy[i] = p / WW; xx[i] = p % WW; }

    u64t acc2[2][NOFF];
    #pragma unroll
    for (int j = 0; j < NOFF; j++) { acc2[0][j] = 0ULL; acc2[1][j] = 0ULL; }

    const float* xb = x + (size_t)b * CIN * HWSZ;
    const int CPZ = CIN / ZSPLIT;   // 32

    for (int c0 = z*CPZ; c0 < z*CPZ + CPZ; c0 += 8) {
        __syncthreads();
        for (int l = tid; l < 8*NOFF*KK2; l += 128) {
            int ci = l / (NOFF*KK2);
            int r  = l % (NOFF*KK2);
            int j  = r / KK2, k = r % KK2;
            ws[l] = w_off[((size_t)(j*CIN + c0 + ci))*KK2 + k];
        }
        __syncthreads();
        #pragma unroll 2
        for (int ci = 0; ci < 8; ci++) {
            const float* xp = xb + (size_t)(c0 + ci) * HWSZ;
            u64t xv2a[9], xv2b[9];
            #pragma unroll
            for (int ky = 0; ky < 3; ky++) {
                #pragma unroll
                for (int kx = 0; kx < 3; kx++) {
                    float v[4];
                    #pragma unroll
                    for (int i = 0; i < 4; i++) {
                        int iy = yy[i] - 1 + ky, ix = xx[i] - 1 + kx;
                        v[i] = (iy >= 0 && iy < HH && ix >= 0 && ix < WW) ? xp[iy*WW + ix] : 0.f;
                    }
                    xv2a[ky*3+kx] = pack2(v[0], v[1]);
                    xv2b[ky*3+kx] = pack2(v[2], v[3]);
                }
            }
            const float* wsc = ws + ci * NOFF * KK2;
            #pragma unroll
            for (int j = 0; j < NOFF; j++) {
                #pragma unroll
                for (int k = 0; k < KK2; k++) {
                    float w = wsc[j*KK2 + k];
                    u64t w2 = pack2(w, w);
                    fma2(acc2[0][j], xv2a[k], w2);
                    fma2(acc2[1][j], xv2b[k], w2);
                }
            }
        }
    }
    size_t zb = (size_t)z * NB * NOFF * HWSZ;
    #pragma unroll
    for (int j = 0; j < NOFF; j++) {
        float2 a = unpack2(acc2[0][j]);
        float2 c = unpack2(acc2[1][j]);
        size_t base = zb + ((size_t)b*NOFF + j)*HWSZ + p0;
        g_off_part[base        ] = a.x;
        g_off_part[base + 128  ] = a.y;
        g_off_part[base + 256  ] = c.x;
        g_off_part[base + 384  ] = c.y;
    }
}

// Kernel A2: sum partials + bias
__global__ void offset_reduce(const float* __restrict__ b_off)
{
    int i = blockIdx.x * 256 + threadIdx.x;
    if (i < NB*NOFF*HWSZ) {
        int j = (i / HWSZ) % NOFF;
        float s = b_off[j];
        #pragma unroll
        for (int z = 0; z < ZSPLIT; z++) s += g_off_part[(size_t)z*NB*NOFF*HWSZ + i];
        g_offset[i] = s;
    }
}

// ---------------------------------------------------------------------------
// Kernel B (fused): wfrag pack + xpair table.
// ---------------------------------------------------------------------------
__global__ void prep(const float* __restrict__ w_def, const float* __restrict__ x)
{
    int i = blockIdx.x * 256 + threadIdx.x;
    if (i < NWF) {
        int idx = i;
        int ii    =  idx        & 3;
        int lane  = (idx >> 2)  & 31;
        int ks    = (idx >> 7)  & 3;
        int mb    = (idx >> 9)  & 15;
        int chunk =  idx >> 13;
        int o = mb*16 + (lane >> 2) + (ii & 1)*8;
        int k = chunk*64 + ks*16 + (lane & 3)*2 + (ii >> 1)*8;
        float w0 = w_def[(size_t)o*CK + k];
        float w1 = w_def[(size_t)o*CK + k + 1];
        __half2 v = __floats2half2_rn(w0, w1);
        g_wfrag[idx] = *(uint32_t*)&v;
    } else {
        int j = i - NWF;
        if (j < NXP) {
            int pi  = j % WP;
            int row = j / WP;              // b*CIN*HH + c*HH + y
            const float* rp = x + (size_t)row * WW;
            float lo = (pi >= 1)      ? rp[pi-1] : 0.f;
            float hi = (pi <= WW - 1) ? rp[pi]   : 0.f;
            __half2 h = __floats2half2_rn(lo, hi);
            g_xpair[j] = *(uint32_t*)&h;
        }
    }
}

// ---------------------------------------------------------------------------
__device__ __forceinline__ void mma16816(float* c, uint4 a, uint32_t b0, uint32_t b1)
{
    asm volatile(
        "mma.sync.aligned.m16n8k16.row.col.f32.f16.f16.f32 "
        "{%0,%1,%2,%3}, {%4,%5,%6,%7}, {%8,%9}, {%0,%1,%2,%3};"
        : "+f"(c[0]), "+f"(c[1]), "+f"(c[2]), "+f"(c[3])
        : "r"(a.x), "r"(a.y), "r"(a.z), "r"(a.w), "r"(b0), "r"(b1));
}

// ---------------------------------------------------------------------------
// Kernel C: fused bilinear-gather + fp16 HMMA, paired idx/weight tables.
// Entry[pl][k2] holds (self, (k2+1)%9) pairs -> one LDS.128 per k-value pair.
// CTA: 64 px x 256 Cout; 256 threads = 8 warps (4 m-rows x 2 n-cols),
// warp tile 64 x 32. grid 576, 2 CTAs/SM.
// ---------------------------------------------------------------------------
__global__ void __launch_bounds__(NT, 2) dcn_hmma(
    const float* __restrict__ x,
    float* __restrict__ out,
    const float* __restrict__ b_def)
{
    extern __shared__ __align__(16) unsigned char smem_raw[];
    int4*  s_idx4 = (int4*) (smem_raw + OFF_IDX);   // [pl*9 + k2]
    uint4* s_wq4  = (uint4*)(smem_raw + OFF_WQ);    // [pl*9 + k2]

    int tid = threadIdx.x, wid = tid >> 5, lane = tid & 31;
    int mrow = wid >> 1, ncol = wid & 1;

    int gp    = blockIdx.x * PX;
    int b     = gp / HWSZ;
    int pbase = gp % HWSZ;

    // Phase 1: pair indices & fp16 corner-product weights, paired tables.
    for (int l = tid; l < KK2*PX; l += NT) {
        int k2 = l >> 6, pl = l & 63;
        int p  = pbase + pl;
        int oy = p / WW, ox = p % WW;
        float offy = g_offset[((size_t)b*NOFF + k2*2    )*HWSZ + p];
        float offx = g_offset[((size_t)b*NOFF + k2*2 + 1)*HWSZ + p];
        int ky = k2 / 3, kx = k2 % 3;
        float py = (float)(oy - 1 + ky) + offy;
        float px = (float)(ox - 1 + kx) + offx;
        float y0f = floorf(py), x0f = floorf(px);
        float wy1 = py - y0f, wy0 = 1.f - wy1;
        float wx1 = px - x0f, wx0 = 1.f - wx1;
        int iy0 = (int)y0f, ix0 = (int)x0f;
        int iy1 = iy0 + 1;
        int pir = ix0 + 1;                       // pair index
        bool inx = (pir >= 0) && (pir <= WP - 1);
        int pi  = min(max(pir, 0), WP - 1);
        bool vy0 = (iy0 >= 0) && (iy0 < HH), vy1 = (iy1 >= 0) && (iy1 < HH);
        int cy0 = min(max(iy0, 0), HH-1), cy1 = min(max(iy1, 0), HH-1);

        float fx0 = inx ? wx0 : 0.f, fx1 = inx ? wx1 : 0.f;
        float fy0 = vy0 ? wy0 : 0.f, fy1 = vy1 ? wy1 : 0.f;
        __half2 wlo = __floats2half2_rn(fy0*fx0, fy0*fx1);
        __half2 whi = __floats2half2_rn(fy1*fx0, fy1*fx1);

        int idx0 = cy0*WP + pi, idx1 = cy1*WP + pi;
        int e2 = (k2 == 0) ? 8 : (k2 - 1);       // entry where this is elem #2

        ((int2*)(s_idx4 + pl*9 + k2))[0] = make_int2(idx0, idx1);
        ((int2*)(s_idx4 + pl*9 + e2))[1] = make_int2(idx0, idx1);
        uint2 wv = make_uint2(*(uint32_t*)&wlo, *(uint32_t*)&whi);
        ((uint2*)(s_wq4 + pl*9 + k2))[0] = wv;
        ((uint2*)(s_wq4 + pl*9 + e2))[1] = wv;
    }
    __syncthreads();

    const uint32_t* xb_pair = g_xpair + (size_t)b * CIN * CSTR;
    const uint4* wfrag4 = (const uint4*)g_wfrag;

    float acc[4][4][4];
    #pragma unroll
    for (int i = 0; i < 4; i++)
        #pragma unroll
        for (int j = 0; j < 4; j++)
            #pragma unroll
            for (int e = 0; e < 4; e++) acc[i][j][e] = 0.f;

    // ---- gather: 2 halves x (batched LDG load phase, then compute+STS) ----
    auto gather_store = [&](int chunk, int bb) {
        uint32_t* sB = (uint32_t*)(smem_raw + bb * BBUF_BYTES);
        int ck0 = chunk * KC;
        #pragma unroll
        for (int half = 0; half < 2; half++) {
            uint32_t u[16];
            #pragma unroll
            for (int e = 0; e < 4; e++) {
                int l  = (half*4 + e)*NT + tid;
                int kp = l >> 6, pl = l & 63;
                int ck = ck0 + kp*2;
                int c  = ck / 9, k2 = ck - c*9;
                int4 ip = s_idx4[pl*9 + k2];
                const uint32_t* xp = xb_pair + (size_t)c * CSTR;
                u[e*4+0] = __ldg(xp + ip.x);
                u[e*4+1] = __ldg(xp + ip.y);
                const uint32_t* xq = xb_pair + (size_t)(c + (k2 == 8)) * CSTR;
                u[e*4+2] = __ldg(xq + ip.z);
                u[e*4+3] = __ldg(xq + ip.w);
            }
            #pragma unroll
            for (int e = 0; e < 4; e++) {
                int l  = (half*4 + e)*NT + tid;
                int kp = l >> 6, pl = l & 63;
                int ck = ck0 + kp*2;
                int c  = ck / 9, k2 = ck - c*9;
                uint4 wq = s_wq4[pl*9 + k2];
                float2 q0 = __half22float2(*(__half2*)&wq.x);
                float2 q1 = __half22float2(*(__half2*)&wq.y);
                float2 a0 = __half22float2(*(__half2*)&u[e*4+0]);
                float2 a1 = __half22float2(*(__half2*)&u[e*4+1]);
                float v0 = q0.x*a0.x + q0.y*a0.y + q1.x*a1.x + q1.y*a1.y;
                q0 = __half22float2(*(__half2*)&wq.z);
                q1 = __half22float2(*(__half2*)&wq.w);
                a0 = __half22float2(*(__half2*)&u[e*4+2]);
                a1 = __half22float2(*(__half2*)&u[e*4+3]);
                float v1 = q0.x*a0.x + q0.y*a0.y + q1.x*a1.x + q1.y*a1.y;
                __half2 hv = __floats2half2_rn(v0, v1);
                sB[kp*BSTRIDE + pl] = *(uint32_t*)&hv;
            }
        }
    };

    gather_store(0, 0);
    __syncthreads();

    #pragma unroll 1
    for (int chunk = 0; chunk < NCHUNK; ++chunk) {
        if (chunk + 1 < NCHUNK) gather_store(chunk + 1, (chunk + 1) & 1);

        uint32_t* sB = (uint32_t*)(smem_raw + (chunk & 1) * BBUF_BYTES);

        #pragma unroll
        for (int ks = 0; ks < 4; ks++) {
            uint32_t bh0[4], bh1[4];
            #pragma unroll
            for (int nb = 0; nb < 4; nb++) {
                int col = ncol*32 + nb*8 + (lane >> 2);
                int kpb = ks*8 + (lane & 3);
                bh0[nb] = sB[ kpb     *BSTRIDE + col];
                bh1[nb] = sB[(kpb + 4)*BSTRIDE + col];
            }
            #pragma unroll
            for (int mb = 0; mb < 4; mb++) {
                int mbg = mrow*4 + mb;
                uint4 a = __ldg(wfrag4 + ((size_t)(chunk*16 + mbg)*4 + ks)*32 + lane);
                #pragma unroll
                for (int nb = 0; nb < 4; nb++)
                    mma16816(acc[mb][nb], a, bh0[nb], bh1[nb]);
            }
        }
        __syncthreads();
    }

    // ---- epilogue: bias + store ----
    #pragma unroll
    for (int mb = 0; mb < 4; mb++) {
        int o0 = mrow*64 + mb*16 + (lane >> 2);
        float bd0 = b_def[o0], bd8 = b_def[o0 + 8];
        float* r0 = out + ((size_t)b*COUT + o0)*HWSZ + pbase + ncol*32 + (lane & 3)*2;
        float* r8 = r0 + (size_t)8*HWSZ;
        #pragma unroll
        for (int nb = 0; nb < 4; nb++) {
            float2 v0 = make_float2(acc[mb][nb][0] + bd0, acc[mb][nb][1] + bd0);
            float2 v8 = make_float2(acc[mb][nb][2] + bd8, acc[mb][nb][3] + bd8);
            *(float2*)(r0 + nb*8) = v0;
            *(float2*)(r8 + nb*8) = v8;
        }
    }
}

// ---------------------------------------------------------------------------
extern "C" void kernel_launch(void* const* d_in, const int* in_sizes, int n_in,
                              void* d_out, int out_size)
{
    const float* x     = (const float*)d_in[0];
    const float* w_off = (const float*)d_in[1];
    const float* b_off = (const float*)d_in[2];
    const float* w_def = (const float*)d_in[3];
    const float* b_def = (const float*)d_in[4];
    float* out = (float*)d_out;

    cudaFuncSetAttribute(dcn_hmma, cudaFuncAttributeMaxDynamicSharedMemorySize, SMEM_BYTES);

    offset_part<<<dim3(HWSZ/512, NB, ZSPLIT), 128>>>(x, w_off);
    prep<<<(NWF + NXP + 255)/256, 256>>>(w_def, x);
    offset_reduce<<<(NB*NOFF*HWSZ + 255)/256, 256>>>(b_off);
    dcn_hmma<<<NB*HWSZ/PX, NT, SMEM_BYTES>>>(x, out, b_def);
}